// round 9
// baseline (speedup 1.0000x reference)
#include <cuda_runtime.h>
#include <cuda_fp16.h>

#define D128 128
#define MAXN 50000
#define MAXE 500000
#define BK 32

// ---------------- scratch (device globals; no allocation allowed) ----------------
__device__ __align__(16) float  g_H1n[MAXN * D128];  // relu(LN(x@node_w1+b1))
__device__ __align__(16) __half g_A[MAXN * D128];    // x @ W_src   (fp16)
__device__ __align__(16) __half g_B[MAXN * D128];    // x @ W_dst   (fp16)
__device__ __align__(16) float  g_S[MAXN * D128];    // segment_sum of edge v
__device__ __align__(16) float  g_T[MAXN * D128];    // H1n @ Wnc
__device__ __align__(16) float  g_deg[MAXN];
__device__ __align__(16) float  g_Wnc[D128 * D128];
__device__ __align__(16) float  g_Wec[D128 * D128];
__device__ __align__(16) float  g_cbias[D128];
__device__ __align__(16) float  g_evec[D128];
// CSR build
__device__ __align__(16) int    g_cnt[MAXN];
__device__ __align__(16) int    g_off[MAXN];
__device__ __align__(16) int    g_cur[MAXN];
__device__ __align__(16) int    g_esrc[MAXE];
__device__ __align__(16) float4 g_ea4[MAXE];
__device__ __align__(16) float  g_ea1[MAXE];
__device__ int g_idx64;

// ---------------- packed fp32x2 helpers (sm_103a FFMA2 path) ----------------
static __device__ __forceinline__ unsigned long long pack2(float x, float y) {
    unsigned long long r;
    asm("mov.b64 %0, {%1,%2};" : "=l"(r) : "f"(x), "f"(y));
    return r;
}
static __device__ __forceinline__ void fma2(unsigned long long& d,
                                            unsigned long long a,
                                            unsigned long long b) {
    asm("fma.rn.f32x2 %0, %1, %2, %0;" : "+l"(d) : "l"(a), "l"(b));
}
static __device__ __forceinline__ float2 unpack2(unsigned long long v) {
    float2 r;
    asm("mov.b64 {%0,%1}, %2;" : "=f"(r.x), "=f"(r.y) : "l"(v));
    return r;
}
static __device__ __forceinline__ unsigned h2u(__half2 h) {
    return *reinterpret_cast<unsigned*>(&h);
}
static __device__ __forceinline__ float2 u2f2(unsigned u) {
    __half2 h = *reinterpret_cast<__half2*>(&u);
    return __half22float2(h);
}

// ---------------- detect idx dtype + zero cnt ----------------
__global__ void detect_zero_kernel(const unsigned int* __restrict__ w, int nwords,
                                   int* __restrict__ cnt, int N)
{
    int i = blockIdx.x * blockDim.x + threadIdx.x;
    if (i < N) cnt[i] = 0;
    if (blockIdx.x == 0) {
        __shared__ int any_nonzero;
        if (threadIdx.x == 0) any_nonzero = 0;
        __syncthreads();
        for (int t = threadIdx.x; t < nwords / 2; t += blockDim.x)
            if (w[2 * t + 1] != 0u) any_nonzero = 1;
        __syncthreads();
        if (threadIdx.x == 0) g_idx64 = any_nonzero ? 0 : 1;
    }
}

// ---------------- CSR: count ----------------
__global__ void count_kernel(const void* __restrict__ ei_raw, int* __restrict__ cnt,
                             int E, int N)
{
    int idx64 = g_idx64;
    for (int e = blockIdx.x * blockDim.x + threadIdx.x; e < E; e += gridDim.x * blockDim.x) {
        int dst;
        if (idx64) dst = (int)((const long long*)ei_raw)[(long long)E + e];
        else       dst = ((const int*)ei_raw)[(long long)E + e];
        dst = min(max(dst, 0), N - 1);
        atomicAdd(cnt + dst, 1);
    }
}

// ---------------- CSR: single-block exclusive scan (1024 threads) ----------------
__global__ void scan_kernel(const int* __restrict__ cnt, int* __restrict__ off,
                            int* __restrict__ cur, int N)
{
    __shared__ int wsum[32];
    int tid = threadIdx.x;
    int chunk = (N + 1023) >> 10;
    int lo = tid * chunk;
    int hi = lo + chunk; if (hi > N) hi = N;
    int s = 0;
    for (int i = lo; i < hi; i++) s += cnt[i];
    int lane = tid & 31, wid = tid >> 5;
    int v = s;
    #pragma unroll
    for (int o = 1; o < 32; o <<= 1) {
        int t = __shfl_up_sync(0xffffffffu, v, o);
        if (lane >= o) v += t;
    }
    if (lane == 31) wsum[wid] = v;
    __syncthreads();
    if (wid == 0) {
        int wv = wsum[lane];
        #pragma unroll
        for (int o = 1; o < 32; o <<= 1) {
            int t = __shfl_up_sync(0xffffffffu, wv, o);
            if (lane >= o) wv += t;
        }
        wsum[lane] = wv;
    }
    __syncthreads();
    int pre = (v - s) + (wid ? wsum[wid - 1] : 0);
    int run = pre;
    for (int i = lo; i < hi; i++) {
        off[i] = run; cur[i] = run; run += cnt[i];
    }
}

// ---------------- CSR: reorder edges by dst ----------------
__global__ void reorder_kernel(const void* __restrict__ ei_raw,
                               const float* __restrict__ ea,
                               int* __restrict__ cur,
                               int* __restrict__ esrc, float4* __restrict__ ea4,
                               float* __restrict__ ea1, int E, int N)
{
    int idx64 = g_idx64;
    for (int e = blockIdx.x * blockDim.x + threadIdx.x; e < E; e += gridDim.x * blockDim.x) {
        int src, dst;
        if (idx64) {
            src = (int)((const long long*)ei_raw)[e];
            dst = (int)((const long long*)ei_raw)[(long long)E + e];
        } else {
            src = ((const int*)ei_raw)[e];
            dst = ((const int*)ei_raw)[(long long)E + e];
        }
        src = min(max(src, 0), N - 1);
        dst = min(max(dst, 0), N - 1);
        int pos = atomicAdd(cur + dst, 1);
        const float* p = ea + (size_t)e * 5;
        esrc[pos] = src;
        ea4[pos] = make_float4(p[0], p[1], p[2], p[3]);
        ea1[pos] = p[4];
    }
}

// ---------------- shared GEMM inner pass ----------------
__device__ __forceinline__ void gemm_pass(
    const float* __restrict__ X, const float* __restrict__ W,
    int n0, int N, int tid, int tx, int ty,
    float* Xs2, float* Ws, unsigned long long (&acc)[8][4])
{
    for (int kk = 0; kk < 128; kk += BK) {
        __syncthreads();
        #pragma unroll
        for (int i = 0; i < 4; i++) {
            int idx = tid + i * 256;
            int row = idx >> 3, q = idx & 7;
            int gr = n0 + row; if (gr > N - 1) gr = N - 1;
            float4 v = *(const float4*)(X + (size_t)gr * 128 + kk + q * 4);
            float* s = Xs2 + row * 64 + q * 8;
            *(float4*)(s)     = make_float4(v.x, v.x, v.y, v.y);
            *(float4*)(s + 4) = make_float4(v.z, v.z, v.w, v.w);
        }
        #pragma unroll
        for (int i = 0; i < 4; i++) {
            int idx = tid + i * 256;
            int kr = idx >> 5, cq = idx & 31;
            float4 v = *(const float4*)(W + (size_t)(kk + kr) * 128 + cq * 4);
            *(float4*)(Ws + kr * 128 + cq * 4) = v;
        }
        __syncthreads();
        #pragma unroll
        for (int k = 0; k < BK; k++) {
            float4 b0 = *(const float4*)(Ws + k * 128 + tx * 4);
            float4 b1 = *(const float4*)(Ws + k * 128 + 64 + tx * 4);
            unsigned long long bp[4];
            bp[0] = pack2(b0.x, b0.y); bp[1] = pack2(b0.z, b0.w);
            bp[2] = pack2(b1.x, b1.y); bp[3] = pack2(b1.z, b1.w);
            #pragma unroll
            for (int i = 0; i < 8; i++) {
                int row = (i < 4) ? (ty * 4 + i) : (64 + ty * 4 + (i - 4));
                unsigned long long a2 =
                    *(const unsigned long long*)(Xs2 + row * 64 + k * 2);
                fma2(acc[i][0], a2, bp[0]);
                fma2(acc[i][1], a2, bp[1]);
                fma2(acc[i][2], a2, bp[2]);
                fma2(acc[i][3], a2, bp[3]);
            }
        }
    }
}

// ---------------- fused N/A/B GEMM (R6 form) ----------------
__global__ __launch_bounds__(256, 2) void gemm_nab_kernel(
    const float* __restrict__ X,
    const float* __restrict__ node_w1, const float* __restrict__ edge_w1,
    const float* __restrict__ bias, const float* __restrict__ g,
    const float* __restrict__ be,
    float* __restrict__ H, __half* __restrict__ A, __half* __restrict__ B,
    int N, int ybase)
{
    __shared__ float Xs2[128 * 64];
    __shared__ float Ws[BK * 128];
    int tid = threadIdx.x, tx = tid & 15, ty = tid >> 4;
    int n0 = blockIdx.x * 128;
    int y = blockIdx.y + ybase;
    const float* W = (y == 0) ? node_w1 : (y == 1 ? edge_w1 : edge_w1 + 128 * 128);

    unsigned long long acc[8][4];
    #pragma unroll
    for (int i = 0; i < 8; i++)
        #pragma unroll
        for (int p = 0; p < 4; p++) acc[i][p] = 0ULL;

    gemm_pass(X, W, n0, N, tid, tx, ty, Xs2, Ws, acc);

    if (y == 0) {
        float4 bi0 = *(const float4*)(bias + tx * 4);
        float4 bi1 = *(const float4*)(bias + 64 + tx * 4);
        float4 gg0 = *(const float4*)(g + tx * 4);
        float4 gg1 = *(const float4*)(g + 64 + tx * 4);
        float4 ee0 = *(const float4*)(be + tx * 4);
        float4 ee1 = *(const float4*)(be + 64 + tx * 4);
        #pragma unroll
        for (int i = 0; i < 8; i++) {
            int row = (i < 4) ? (ty * 4 + i) : (64 + ty * 4 + (i - 4));
            int gr = n0 + row;
            float2 f0 = unpack2(acc[i][0]), f1 = unpack2(acc[i][1]);
            float2 f2 = unpack2(acc[i][2]), f3 = unpack2(acc[i][3]);
            float v[8] = { f0.x + bi0.x, f0.y + bi0.y, f1.x + bi0.z, f1.y + bi0.w,
                           f2.x + bi1.x, f2.y + bi1.y, f3.x + bi1.z, f3.y + bi1.w };
            float s = 0.f, ss = 0.f;
            #pragma unroll
            for (int j = 0; j < 8; j++) { s += v[j]; ss += v[j] * v[j]; }
            #pragma unroll
            for (int o = 8; o; o >>= 1) {
                s  += __shfl_xor_sync(0xffffffffu, s,  o);
                ss += __shfl_xor_sync(0xffffffffu, ss, o);
            }
            float mean = s * (1.0f / 128.0f);
            float var  = ss * (1.0f / 128.0f) - mean * mean;
            float rs   = rsqrtf(var + 1e-5f);
            float o0 = fmaxf(0.f, (v[0] - mean) * rs * gg0.x + ee0.x);
            float o1 = fmaxf(0.f, (v[1] - mean) * rs * gg0.y + ee0.y);
            float o2 = fmaxf(0.f, (v[2] - mean) * rs * gg0.z + ee0.z);
            float o3 = fmaxf(0.f, (v[3] - mean) * rs * gg0.w + ee0.w);
            float o4 = fmaxf(0.f, (v[4] - mean) * rs * gg1.x + ee1.x);
            float o5 = fmaxf(0.f, (v[5] - mean) * rs * gg1.y + ee1.y);
            float o6 = fmaxf(0.f, (v[6] - mean) * rs * gg1.z + ee1.z);
            float o7 = fmaxf(0.f, (v[7] - mean) * rs * gg1.w + ee1.w);
            if (gr < N) {
                *(float4*)(H + (size_t)gr * 128 + tx * 4)      = make_float4(o0, o1, o2, o3);
                *(float4*)(H + (size_t)gr * 128 + 64 + tx * 4) = make_float4(o4, o5, o6, o7);
            }
        }
    } else {
        __half* Yh = (y == 1) ? A : B;
        #pragma unroll
        for (int i = 0; i < 8; i++) {
            int row = (i < 4) ? (ty * 4 + i) : (64 + ty * 4 + (i - 4));
            int gr = n0 + row;
            if (gr < N) {
                float2 f0 = unpack2(acc[i][0]), f1 = unpack2(acc[i][1]);
                float2 f2 = unpack2(acc[i][2]), f3 = unpack2(acc[i][3]);
                uint2 u0, u1;
                u0.x = h2u(__floats2half2_rn(f0.x, f0.y));
                u0.y = h2u(__floats2half2_rn(f1.x, f1.y));
                u1.x = h2u(__floats2half2_rn(f2.x, f2.y));
                u1.y = h2u(__floats2half2_rn(f3.x, f3.y));
                *(uint2*)(Yh + (size_t)gr * 128 + tx * 4)      = u0;
                *(uint2*)(Yh + (size_t)gr * 128 + 64 + tx * 4) = u1;
            }
        }
    }
}

// ---------------- T = H @ Wnc ----------------
__global__ __launch_bounds__(256, 2) void gemm_t_kernel(
    const float* __restrict__ H, float* __restrict__ T, int N)
{
    __shared__ float Xs2[128 * 64];
    __shared__ float Ws[BK * 128];
    int tid = threadIdx.x, tx = tid & 15, ty = tid >> 4;
    int n0 = blockIdx.x * 128;
    unsigned long long acc[8][4];
    #pragma unroll
    for (int i = 0; i < 8; i++)
        #pragma unroll
        for (int p = 0; p < 4; p++) acc[i][p] = 0ULL;

    gemm_pass(H, g_Wnc, n0, N, tid, tx, ty, Xs2, Ws, acc);

    #pragma unroll
    for (int i = 0; i < 8; i++) {
        int row = (i < 4) ? (ty * 4 + i) : (64 + ty * 4 + (i - 4));
        int gr = n0 + row;
        if (gr < N) {
            float2 f0 = unpack2(acc[i][0]), f1 = unpack2(acc[i][1]);
            float2 f2 = unpack2(acc[i][2]), f3 = unpack2(acc[i][3]);
            *(float4*)(T + (size_t)gr * 128 + tx * 4)      = make_float4(f0.x, f0.y, f1.x, f1.y);
            *(float4*)(T + (size_t)gr * 128 + 64 + tx * 4) = make_float4(f2.x, f2.y, f3.x, f3.y);
        }
    }
}

// ---------------- final: out = LN(T + S@Wec + x + cbias + deg*evec) ----------------
__global__ __launch_bounds__(256, 2) void final_kernel(
    const float* __restrict__ T, const float* __restrict__ S,
    const float* __restrict__ x, const float* __restrict__ deg,
    const float* __restrict__ lng, const float* __restrict__ lnb,
    float* __restrict__ Y, int N)
{
    __shared__ float Xs2[128 * 64];
    __shared__ float Ws[BK * 128];
    int tid = threadIdx.x, tx = tid & 15, ty = tid >> 4;
    int n0 = blockIdx.x * 128;
    unsigned long long acc[8][4];
    #pragma unroll
    for (int i = 0; i < 8; i++)
        #pragma unroll
        for (int p = 0; p < 4; p++) acc[i][p] = 0ULL;

    gemm_pass(S, g_Wec, n0, N, tid, tx, ty, Xs2, Ws, acc);

    float4 cb0 = *(const float4*)(g_cbias + tx * 4);
    float4 cb1 = *(const float4*)(g_cbias + 64 + tx * 4);
    float4 ev0 = *(const float4*)(g_evec + tx * 4);
    float4 ev1 = *(const float4*)(g_evec + 64 + tx * 4);
    float4 gg0 = *(const float4*)(lng + tx * 4);
    float4 gg1 = *(const float4*)(lng + 64 + tx * 4);
    float4 bb0 = *(const float4*)(lnb + tx * 4);
    float4 bb1 = *(const float4*)(lnb + 64 + tx * 4);

    #pragma unroll
    for (int i = 0; i < 8; i++) {
        int row = (i < 4) ? (ty * 4 + i) : (64 + ty * 4 + (i - 4));
        int gr = n0 + row;
        int gl = (gr > N - 1) ? (N - 1) : gr;
        float d = deg[gl];
        float4 xr0 = *(const float4*)(x + (size_t)gl * 128 + tx * 4);
        float4 xr1 = *(const float4*)(x + (size_t)gl * 128 + 64 + tx * 4);
        float4 tr0 = *(const float4*)(T + (size_t)gl * 128 + tx * 4);
        float4 tr1 = *(const float4*)(T + (size_t)gl * 128 + 64 + tx * 4);
        float2 f0 = unpack2(acc[i][0]), f1 = unpack2(acc[i][1]);
        float2 f2 = unpack2(acc[i][2]), f3 = unpack2(acc[i][3]);
        float v[8];
        v[0] = f0.x + tr0.x + xr0.x + cb0.x + d * ev0.x;
        v[1] = f0.y + tr0.y + xr0.y + cb0.y + d * ev0.y;
        v[2] = f1.x + tr0.z + xr0.z + cb0.z + d * ev0.z;
        v[3] = f1.y + tr0.w + xr0.w + cb0.w + d * ev0.w;
        v[4] = f2.x + tr1.x + xr1.x + cb1.x + d * ev1.x;
        v[5] = f2.y + tr1.y + xr1.y + cb1.y + d * ev1.y;
        v[6] = f3.x + tr1.z + xr1.z + cb1.z + d * ev1.z;
        v[7] = f3.y + tr1.w + xr1.w + cb1.w + d * ev1.w;
        float s = 0.f, ss = 0.f;
        #pragma unroll
        for (int j = 0; j < 8; j++) { s += v[j]; ss += v[j] * v[j]; }
        #pragma unroll
        for (int o = 8; o; o >>= 1) {
            s  += __shfl_xor_sync(0xffffffffu, s,  o);
            ss += __shfl_xor_sync(0xffffffffu, ss, o);
        }
        float mean = s * (1.0f / 128.0f);
        float var  = ss * (1.0f / 128.0f) - mean * mean;
        float rs   = rsqrtf(var + 1e-5f);
        float o0 = (v[0] - mean) * rs * gg0.x + bb0.x;
        float o1 = (v[1] - mean) * rs * gg0.y + bb0.y;
        float o2 = (v[2] - mean) * rs * gg0.z + bb0.z;
        float o3 = (v[3] - mean) * rs * gg0.w + bb0.w;
        float o4 = (v[4] - mean) * rs * gg1.x + bb1.x;
        float o5 = (v[5] - mean) * rs * gg1.y + bb1.y;
        float o6 = (v[6] - mean) * rs * gg1.z + bb1.z;
        float o7 = (v[7] - mean) * rs * gg1.w + bb1.w;
        if (gr < N) {
            *(float4*)(Y + (size_t)gr * 128 + tx * 4)      = make_float4(o0, o1, o2, o3);
            *(float4*)(Y + (size_t)gr * 128 + 64 + tx * 4) = make_float4(o4, o5, o6, o7);
        }
    }
}

// ---------------- aggregation kernel: one warp per dst node, NO atomics ----------------
__global__ __launch_bounds__(256, 4) void agg_kernel(
    const __half* __restrict__ A, const __half* __restrict__ B,
    const int* __restrict__ off, const int* __restrict__ cnt,
    const int* __restrict__ esrc, const float4* __restrict__ ea4,
    const float* __restrict__ ea1,
    const float* __restrict__ W5, const float* __restrict__ eb1,
    const float* __restrict__ g1, const float* __restrict__ be1,
    float* __restrict__ S, float* __restrict__ deg, int N)
{
    __shared__ float sW5[5 * 128];
    __shared__ float sb[128], sg[128], sbe[128];
    int tid = threadIdx.x;
    for (int i = tid; i < 5 * 128; i += 256) sW5[i] = W5[i];
    if (tid < 128) { sb[tid] = eb1[tid]; sg[tid] = g1[tid]; sbe[tid] = be1[tid]; }
    __syncthreads();

    int lane = tid & 31;
    int gw = (blockIdx.x * 256 + tid) >> 5;
    int nw = (gridDim.x * 256) >> 5;
    int c = lane * 4;

    float4 w0 = *(const float4*)(sW5 + 0 * 128 + c);
    float4 w1 = *(const float4*)(sW5 + 1 * 128 + c);
    float4 w2 = *(const float4*)(sW5 + 2 * 128 + c);
    float4 w3 = *(const float4*)(sW5 + 3 * 128 + c);
    float4 w4 = *(const float4*)(sW5 + 4 * 128 + c);
    float4 sb4 = *(const float4*)(sb + c);
    float4 sg4 = *(const float4*)(sg + c);
    float4 se4 = *(const float4*)(sbe + c);

    for (int d = gw; d < N; d += nw) {
        int start = __ldg(off + d);
        int n     = __ldg(cnt + d);
        float a0 = 0.f, a1 = 0.f, a2 = 0.f, a3 = 0.f;

        if (n > 0) {
            uint2 rbu = __ldg((const uint2*)(B + (size_t)d * 128 + c));
            float2 blo = u2f2(rbu.x), bhi = u2f2(rbu.y);

            for (int k = 0; k < n; k += 2) {
                int i0 = start + k;
                bool v1 = (k + 1 < n);
                int i1 = v1 ? i0 + 1 : i0;

                int s0 = __ldg(esrc + i0);
                int s1 = __ldg(esrc + i1);
                float4 eA = __ldg(ea4 + i0);
                float  e4a = __ldg(ea1 + i0);
                float4 eB = __ldg(ea4 + i1);
                float  e4b = __ldg(ea1 + i1);

                uint2 ra0 = __ldg((const uint2*)(A + (size_t)s0 * 128 + c));
                uint2 ra1 = __ldg((const uint2*)(A + (size_t)s1 * 128 + c));
                float2 x0lo = u2f2(ra0.x), x0hi = u2f2(ra0.y);
                float2 x1lo = u2f2(ra1.x), x1hi = u2f2(ra1.y);

                float b00 = sb4.x + blo.x + eA.x * w0.x + eA.y * w1.x + eA.z * w2.x + eA.w * w3.x + e4a * w4.x;
                float b01 = sb4.y + blo.y + eA.x * w0.y + eA.y * w1.y + eA.z * w2.y + eA.w * w3.y + e4a * w4.y;
                float b02 = sb4.z + bhi.x + eA.x * w0.z + eA.y * w1.z + eA.z * w2.z + eA.w * w3.z + e4a * w4.z;
                float b03 = sb4.w + bhi.y + eA.x * w0.w + eA.y * w1.w + eA.z * w2.w + eA.w * w3.w + e4a * w4.w;
                float p00 = x0lo.x + b00;
                float p01 = x0lo.y + b01;
                float p02 = x0hi.x + b02;
                float p03 = x0hi.y + b03;

                float b10 = sb4.x + blo.x + eB.x * w0.x + eB.y * w1.x + eB.z * w2.x + eB.w * w3.x + e4b * w4.x;
                float b11 = sb4.y + blo.y + eB.x * w0.y + eB.y * w1.y + eB.z * w2.y + eB.w * w3.y + e4b * w4.y;
                float b12 = sb4.z + bhi.x + eB.x * w0.z + eB.y * w1.z + eB.z * w2.z + eB.w * w3.z + e4b * w4.z;
                float b13 = sb4.w + bhi.y + eB.x * w0.w + eB.y * w1.w + eB.z * w2.w + eB.w * w3.w + e4b * w4.w;
                float p10 = x1lo.x + b10;
                float p11 = x1lo.y + b11;
                float p12 = x1hi.x + b12;
                float p13 = x1hi.y + b13;

                float su0 = p00 + p01 + p02 + p03;
                float q0  = p00 * p00 + p01 * p01 + p02 * p02 + p03 * p03;
                float su1 = p10 + p11 + p12 + p13;
                float q1  = p10 * p10 + p11 * p11 + p12 * p12 + p13 * p13;
                #pragma unroll
                for (int o = 16; o; o >>= 1) {
                    su0 += __shfl_xor_sync(0xffffffffu, su0, o);
                    q0  += __shfl_xor_sync(0xffffffffu, q0,  o);
                    su1 += __shfl_xor_sync(0xffffffffu, su1, o);
                    q1  += __shfl_xor_sync(0xffffffffu, q1,  o);
                }
                float mean0 = su0 * (1.0f / 128.0f);
                float rs0   = rsqrtf(q0 * (1.0f / 128.0f) - mean0 * mean0 + 1e-5f);
                float mean1 = su1 * (1.0f / 128.0f);
                float rs1   = rsqrtf(q1 * (1.0f / 128.0f) - mean1 * mean1 + 1e-5f);

                a0 += fmaxf(0.f, (p00 - mean0) * rs0 * sg4.x + se4.x);
                a1 += fmaxf(0.f, (p01 - mean0) * rs0 * sg4.y + se4.y);
                a2 += fmaxf(0.f, (p02 - mean0) * rs0 * sg4.z + se4.z);
                a3 += fmaxf(0.f, (p03 - mean0) * rs0 * sg4.w + se4.w);
                if (v1) {
                    a0 += fmaxf(0.f, (p10 - mean1) * rs1 * sg4.x + se4.x);
                    a1 += fmaxf(0.f, (p11 - mean1) * rs1 * sg4.y + se4.y);
                    a2 += fmaxf(0.f, (p12 - mean1) * rs1 * sg4.z + se4.z);
                    a3 += fmaxf(0.f, (p13 - mean1) * rs1 * sg4.w + se4.w);
                }
            }
        }
        *(float4*)(S + (size_t)d * 128 + c) = make_float4(a0, a1, a2, a3);
        if (lane == 0) deg[d] = (float)n;
    }
}

// ---------------- prep kernel ----------------
__global__ __launch_bounds__(256, 2) void prep_kernel(
    const float* __restrict__ w2n, const float* __restrict__ w2e,
    const float* __restrict__ U,
    const float* __restrict__ bn2, const float* __restrict__ be2,
    const float* __restrict__ ub,
    float* __restrict__ Wnc, float* __restrict__ Wec,
    float* __restrict__ cb, float* __restrict__ ev)
{
    __shared__ float Xs2[128 * 64];
    __shared__ float Ws[BK * 128];
    int tid = threadIdx.x, tx = tid & 15, ty = tid >> 4;
    int y = blockIdx.y;

    if (y == 2) {
        int j = tid & 127, h = tid >> 7;
        float a = 0.f, b = 0.f;
        int m0 = h * 64;
        #pragma unroll 16
        for (int m = m0; m < m0 + 64; m++) {
            a += bn2[m] * U[m * 128 + j];
            b += be2[m] * U[(128 + m) * 128 + j];
        }
        Xs2[tid] = a;
        Xs2[512 + tid] = b;
        __syncthreads();
        if (h == 0) {
            cb[j] = Xs2[j] + Xs2[128 + j] + ub[j];
            ev[j] = Xs2[512 + j] + Xs2[640 + j];
        }
        return;
    }

    const float* X = y ? w2e : w2n;
    const float* W = y ? (U + 128 * 128) : U;
    float* out = y ? Wec : Wnc;

    unsigned long long acc[8][4];
    #pragma unroll
    for (int i = 0; i < 8; i++)
        #pragma unroll
        for (int p = 0; p < 4; p++) acc[i][p] = 0ULL;

    gemm_pass(X, W, 0, 128, tid, tx, ty, Xs2, Ws, acc);

    #pragma unroll
    for (int i = 0; i < 8; i++) {
        int row = (i < 4) ? (ty * 4 + i) : (64 + ty * 4 + (i - 4));
        float2 f0 = unpack2(acc[i][0]), f1 = unpack2(acc[i][1]);
        float2 f2 = unpack2(acc[i][2]), f3 = unpack2(acc[i][3]);
        *(float4*)(out + (size_t)row * 128 + tx * 4)      = make_float4(f0.x, f0.y, f1.x, f1.y);
        *(float4*)(out + (size_t)row * 128 + 64 + tx * 4) = make_float4(f2.x, f2.y, f3.x, f3.y);
    }
}

// ---------------- launch ----------------
extern "C" void kernel_launch(void* const* d_in, const int* in_sizes, int n_in,
                              void* d_out, int out_size)
{
    const float* x         = (const float*)d_in[0];
    const float* edge_attr = (const float*)d_in[1];
    const float* node_w1   = (const float*)d_in[3];
    const float* node_b1   = (const float*)d_in[4];
    const float* node_g1   = (const float*)d_in[5];
    const float* node_be1  = (const float*)d_in[6];
    const float* node_w2   = (const float*)d_in[7];
    const float* node_b2   = (const float*)d_in[8];
    const float* edge_w1   = (const float*)d_in[9];
    const float* edge_b1   = (const float*)d_in[10];
    const float* edge_g1   = (const float*)d_in[11];
    const float* edge_be1  = (const float*)d_in[12];
    const float* edge_w2   = (const float*)d_in[13];
    const float* edge_b2   = (const float*)d_in[14];
    const float* upd_w     = (const float*)d_in[15];
    const float* upd_b     = (const float*)d_in[16];
    const float* ln_g      = (const float*)d_in[17];
    const float* ln_b      = (const float*)d_in[18];
    const void*  ei        = d_in[19];
    float* out = (float*)d_out;

    int N = in_sizes[0] / 128;
    int E = in_sizes[19] / 2;

    float *pH, *pS, *pT, *pdeg, *pWnc, *pWec, *pcb, *pev, *pea1;
    __half *pA, *pB;
    int *pcnt, *poff, *pcur, *pesrc;
    float4 *pea4;
    cudaGetSymbolAddress((void**)&pH,    g_H1n);
    cudaGetSymbolAddress((void**)&pA,    g_A);
    cudaGetSymbolAddress((void**)&pB,    g_B);
    cudaGetSymbolAddress((void**)&pS,    g_S);
    cudaGetSymbolAddress((void**)&pT,    g_T);
    cudaGetSymbolAddress((void**)&pdeg,  g_deg);
    cudaGetSymbolAddress((void**)&pWnc,  g_Wnc);
    cudaGetSymbolAddress((void**)&pWec,  g_Wec);
    cudaGetSymbolAddress((void**)&pcb,   g_cbias);
    cudaGetSymbolAddress((void**)&pev,   g_evec);
    cudaGetSymbolAddress((void**)&pcnt,  g_cnt);
    cudaGetSymbolAddress((void**)&poff,  g_off);
    cudaGetSymbolAddress((void**)&pcur,  g_cur);
    cudaGetSymbolAddress((void**)&pesrc, g_esrc);
    cudaGetSymbolAddress((void**)&pea4,  g_ea4);
    cudaGetSymbolAddress((void**)&pea1,  g_ea1);

    static cudaStream_t s1 = 0;
    static cudaEvent_t eFork = 0, eCSR = 0, eJoin = 0;
    if (!s1) cudaStreamCreateWithFlags(&s1, cudaStreamNonBlocking);
    if (!eFork) cudaEventCreateWithFlags(&eFork, cudaEventDisableTiming);
    if (!eCSR) cudaEventCreateWithFlags(&eCSR, cudaEventDisableTiming);
    if (!eJoin) cudaEventCreateWithFlags(&eJoin, cudaEventDisableTiming);

    cudaStream_t s0 = cudaStreamLegacy;
    {
        cudaStreamCaptureStatus st = cudaStreamCaptureStatusNone;
        if (cudaStreamIsCapturing(cudaStreamLegacy, &st) == cudaSuccess &&
            st == cudaStreamCaptureStatusActive) {
            s0 = cudaStreamLegacy;
        } else {
            cudaStreamCaptureStatus st2 = cudaStreamCaptureStatusNone;
            if (cudaStreamIsCapturing(cudaStreamPerThread, &st2) == cudaSuccess &&
                st2 == cudaStreamCaptureStatusActive) {
                s0 = cudaStreamPerThread;
            }
        }
    }

    int gb = (N + 127) / 128;
    int nwords = 2 * E; if (nwords > 1024) nwords = 1024;

    // fork
    cudaEventRecord(eFork, s0);
    cudaStreamWaitEvent(s1, eFork, 0);

    // s0 #1: A,B GEMMs (critical path head)
    gemm_nab_kernel<<<dim3(gb, 2), 256, 0, s0>>>(x, node_w1, edge_w1,
                                                 node_b1, node_g1, node_be1,
                                                 pH, pA, pB, N, /*ybase=*/1);

    // s1: CSR build chain (hidden under AB GEMM)
    detect_zero_kernel<<<(N + 255) / 256, 256, 0, s1>>>(
        (const unsigned int*)ei, nwords, pcnt, N);
    count_kernel<<<592, 256, 0, s1>>>(ei, pcnt, E, N);
    scan_kernel<<<1, 1024, 0, s1>>>(pcnt, poff, pcur, N);
    reorder_kernel<<<592, 256, 0, s1>>>(ei, edge_attr, pcur, pesrc, pea4, pea1, E, N);
    cudaEventRecord(eCSR, s1);

    // s1: prep (weight folding)
    prep_kernel<<<dim3(1, 3), 256, 0, s1>>>(node_w2, edge_w2, upd_w,
                                            node_b2, edge_b2, upd_b,
                                            pWnc, pWec, pcb, pev);

    // s0: aggregation (needs AB GEMM on s0 + CSR from s1); no atomics
    cudaStreamWaitEvent(s0, eCSR, 0);
    agg_kernel<<<592, 256, 0, s0>>>(pA, pB, poff, pcnt, pesrc, pea4, pea1,
                                    edge_w1 + 256 * 128, edge_b1, edge_g1, edge_be1,
                                    pS, pdeg, N);

    // s1: H GEMM + T = H @ Wnc (overlap aggregation)
    gemm_nab_kernel<<<dim3(gb, 1), 256, 0, s1>>>(x, node_w1, edge_w1,
                                                 node_b1, node_g1, node_be1,
                                                 pH, pA, pB, N, /*ybase=*/0);
    gemm_t_kernel<<<gb, 256, 0, s1>>>(pH, pT, N);

    // join
    cudaEventRecord(eJoin, s1);
    cudaStreamWaitEvent(s0, eJoin, 0);

    // s0: final
    final_kernel<<<gb, 256, 0, s0>>>(pT, pS, x, pdeg, ln_g, ln_b, out, N);
}

// round 10
// speedup vs baseline: 1.1997x; 1.1997x over previous
#include <cuda_runtime.h>
#include <cuda_fp16.h>

#define D128 128
#define MAXN 50000
#define MAXE 500000
#define BK 32

// ---------------- scratch (device globals; no allocation allowed) ----------------
__device__ __align__(16) float  g_H1n[MAXN * D128];  // relu(LN(x@node_w1+b1))
__device__ __align__(16) __half g_A[MAXN * D128];    // x @ W_src   (fp16)
__device__ __align__(16) __half g_B[MAXN * D128];    // x @ W_dst   (fp16)
__device__ __align__(16) float  g_S[MAXN * D128];    // segment_sum of edge v
__device__ __align__(16) float  g_T[MAXN * D128];    // H1n @ Wnc
__device__ __align__(16) float  g_deg[MAXN];
__device__ __align__(16) float  g_Wnc[D128 * D128];
__device__ __align__(16) float  g_Wec[D128 * D128];
__device__ __align__(16) float  g_cbias[D128];
__device__ __align__(16) float  g_evec[D128];
// CSR build
__device__ __align__(16) int    g_cnt[MAXN];
__device__ __align__(16) int    g_loc[MAXN];
__device__ __align__(16) int    g_btot[64];
__device__ __align__(16) int    g_off[MAXN];
__device__ __align__(16) int    g_cur[MAXN];
__device__ __align__(16) int    g_esrc[MAXE];
__device__ __align__(16) float4 g_ea4[MAXE];
__device__ __align__(16) float  g_ea1[MAXE];
__device__ int g_idx64;

// ---------------- packed fp32x2 helpers (sm_103a FFMA2 path) ----------------
static __device__ __forceinline__ unsigned long long pack2(float x, float y) {
    unsigned long long r;
    asm("mov.b64 %0, {%1,%2};" : "=l"(r) : "f"(x), "f"(y));
    return r;
}
static __device__ __forceinline__ void fma2(unsigned long long& d,
                                            unsigned long long a,
                                            unsigned long long b) {
    asm("fma.rn.f32x2 %0, %1, %2, %0;" : "+l"(d) : "l"(a), "l"(b));
}
static __device__ __forceinline__ float2 unpack2(unsigned long long v) {
    float2 r;
    asm("mov.b64 {%0,%1}, %2;" : "=f"(r.x), "=f"(r.y) : "l"(v));
    return r;
}
static __device__ __forceinline__ unsigned h2u(__half2 h) {
    return *reinterpret_cast<unsigned*>(&h);
}
static __device__ __forceinline__ float2 u2f2(unsigned u) {
    __half2 h = *reinterpret_cast<__half2*>(&u);
    return __half22float2(h);
}

// ---------------- detect idx dtype + zero cnt ----------------
__global__ void detect_zero_kernel(const unsigned int* __restrict__ w, int nwords,
                                   int* __restrict__ cnt, int N)
{
    int i = blockIdx.x * blockDim.x + threadIdx.x;
    if (i < N) cnt[i] = 0;
    if (blockIdx.x == 0) {
        __shared__ int any_nonzero;
        if (threadIdx.x == 0) any_nonzero = 0;
        __syncthreads();
        for (int t = threadIdx.x; t < nwords / 2; t += blockDim.x)
            if (w[2 * t + 1] != 0u) any_nonzero = 1;
        __syncthreads();
        if (threadIdx.x == 0) g_idx64 = any_nonzero ? 0 : 1;
    }
}

// ---------------- CSR: count ----------------
__global__ void count_kernel(const void* __restrict__ ei_raw, int* __restrict__ cnt,
                             int E, int N)
{
    int idx64 = g_idx64;
    for (int e = blockIdx.x * blockDim.x + threadIdx.x; e < E; e += gridDim.x * blockDim.x) {
        int dst;
        if (idx64) dst = (int)((const long long*)ei_raw)[(long long)E + e];
        else       dst = ((const int*)ei_raw)[(long long)E + e];
        dst = min(max(dst, 0), N - 1);
        atomicAdd(cnt + dst, 1);
    }
}

// ---------------- CSR scan phase 1: per-block exclusive scan (1024/block) ----------------
__global__ void scan_local_kernel(const int* __restrict__ cnt, int* __restrict__ loc,
                                  int* __restrict__ btot, int N)
{
    __shared__ int wsum[32];
    int t = threadIdx.x;
    int i = blockIdx.x * 1024 + t;
    int s = (i < N) ? cnt[i] : 0;
    int lane = t & 31, wid = t >> 5;
    int v = s;
    #pragma unroll
    for (int o = 1; o < 32; o <<= 1) {
        int u = __shfl_up_sync(0xffffffffu, v, o);
        if (lane >= o) v += u;
    }
    if (lane == 31) wsum[wid] = v;
    __syncthreads();
    if (wid == 0) {
        int wv = wsum[lane];
        #pragma unroll
        for (int o = 1; o < 32; o <<= 1) {
            int u = __shfl_up_sync(0xffffffffu, wv, o);
            if (lane >= o) wv += u;
        }
        wsum[lane] = wv;
    }
    __syncthreads();
    int pre = (v - s) + (wid ? wsum[wid - 1] : 0);   // exclusive within block
    if (i < N) loc[i] = pre;
    if (t == 1023) btot[blockIdx.x] = pre + s;       // block total
}

// ---------------- CSR scan phase 2: add block-prefix, write off/cur ----------------
__global__ void scan_fix_kernel(const int* __restrict__ loc, const int* __restrict__ btot,
                                int* __restrict__ off, int* __restrict__ cur, int N)
{
    int b = blockIdx.x;
    int base = 0;
    for (int k = 0; k < b; k++) base += btot[k];     // <=49 L2-hot values
    int i = b * 1024 + threadIdx.x;
    if (i < N) {
        int o = loc[i] + base;
        off[i] = o;
        cur[i] = o;
    }
}

// ---------------- CSR: reorder edges by dst ----------------
__global__ void reorder_kernel(const void* __restrict__ ei_raw,
                               const float* __restrict__ ea,
                               int* __restrict__ cur,
                               int* __restrict__ esrc, float4* __restrict__ ea4,
                               float* __restrict__ ea1, int E, int N)
{
    int idx64 = g_idx64;
    for (int e = blockIdx.x * blockDim.x + threadIdx.x; e < E; e += gridDim.x * blockDim.x) {
        int src, dst;
        if (idx64) {
            src = (int)((const long long*)ei_raw)[e];
            dst = (int)((const long long*)ei_raw)[(long long)E + e];
        } else {
            src = ((const int*)ei_raw)[e];
            dst = ((const int*)ei_raw)[(long long)E + e];
        }
        src = min(max(src, 0), N - 1);
        dst = min(max(dst, 0), N - 1);
        int pos = atomicAdd(cur + dst, 1);
        const float* p = ea + (size_t)e * 5;
        esrc[pos] = src;
        ea4[pos] = make_float4(p[0], p[1], p[2], p[3]);
        ea1[pos] = p[4];
    }
}

// ---------------- shared GEMM inner pass ----------------
__device__ __forceinline__ void gemm_pass(
    const float* __restrict__ X, const float* __restrict__ W,
    int n0, int N, int tid, int tx, int ty,
    float* Xs2, float* Ws, unsigned long long (&acc)[8][4])
{
    for (int kk = 0; kk < 128; kk += BK) {
        __syncthreads();
        #pragma unroll
        for (int i = 0; i < 4; i++) {
            int idx = tid + i * 256;
            int row = idx >> 3, q = idx & 7;
            int gr = n0 + row; if (gr > N - 1) gr = N - 1;
            float4 v = *(const float4*)(X + (size_t)gr * 128 + kk + q * 4);
            float* s = Xs2 + row * 64 + q * 8;
            *(float4*)(s)     = make_float4(v.x, v.x, v.y, v.y);
            *(float4*)(s + 4) = make_float4(v.z, v.z, v.w, v.w);
        }
        #pragma unroll
        for (int i = 0; i < 4; i++) {
            int idx = tid + i * 256;
            int kr = idx >> 5, cq = idx & 31;
            float4 v = *(const float4*)(W + (size_t)(kk + kr) * 128 + cq * 4);
            *(float4*)(Ws + kr * 128 + cq * 4) = v;
        }
        __syncthreads();
        #pragma unroll
        for (int k = 0; k < BK; k++) {
            float4 b0 = *(const float4*)(Ws + k * 128 + tx * 4);
            float4 b1 = *(const float4*)(Ws + k * 128 + 64 + tx * 4);
            unsigned long long bp[4];
            bp[0] = pack2(b0.x, b0.y); bp[1] = pack2(b0.z, b0.w);
            bp[2] = pack2(b1.x, b1.y); bp[3] = pack2(b1.z, b1.w);
            #pragma unroll
            for (int i = 0; i < 8; i++) {
                int row = (i < 4) ? (ty * 4 + i) : (64 + ty * 4 + (i - 4));
                unsigned long long a2 =
                    *(const unsigned long long*)(Xs2 + row * 64 + k * 2);
                fma2(acc[i][0], a2, bp[0]);
                fma2(acc[i][1], a2, bp[1]);
                fma2(acc[i][2], a2, bp[2]);
                fma2(acc[i][3], a2, bp[3]);
            }
        }
    }
}

// ---------------- fused N/A/B GEMM ----------------
__global__ __launch_bounds__(256, 2) void gemm_nab_kernel(
    const float* __restrict__ X,
    const float* __restrict__ node_w1, const float* __restrict__ edge_w1,
    const float* __restrict__ bias, const float* __restrict__ g,
    const float* __restrict__ be,
    float* __restrict__ H, __half* __restrict__ A, __half* __restrict__ B,
    int N, int ybase)
{
    __shared__ float Xs2[128 * 64];
    __shared__ float Ws[BK * 128];
    int tid = threadIdx.x, tx = tid & 15, ty = tid >> 4;
    int n0 = blockIdx.x * 128;
    int y = blockIdx.y + ybase;
    const float* W = (y == 0) ? node_w1 : (y == 1 ? edge_w1 : edge_w1 + 128 * 128);

    unsigned long long acc[8][4];
    #pragma unroll
    for (int i = 0; i < 8; i++)
        #pragma unroll
        for (int p = 0; p < 4; p++) acc[i][p] = 0ULL;

    gemm_pass(X, W, n0, N, tid, tx, ty, Xs2, Ws, acc);

    if (y == 0) {
        float4 bi0 = *(const float4*)(bias + tx * 4);
        float4 bi1 = *(const float4*)(bias + 64 + tx * 4);
        float4 gg0 = *(const float4*)(g + tx * 4);
        float4 gg1 = *(const float4*)(g + 64 + tx * 4);
        float4 ee0 = *(const float4*)(be + tx * 4);
        float4 ee1 = *(const float4*)(be + 64 + tx * 4);
        #pragma unroll
        for (int i = 0; i < 8; i++) {
            int row = (i < 4) ? (ty * 4 + i) : (64 + ty * 4 + (i - 4));
            int gr = n0 + row;
            float2 f0 = unpack2(acc[i][0]), f1 = unpack2(acc[i][1]);
            float2 f2 = unpack2(acc[i][2]), f3 = unpack2(acc[i][3]);
            float v[8] = { f0.x + bi0.x, f0.y + bi0.y, f1.x + bi0.z, f1.y + bi0.w,
                           f2.x + bi1.x, f2.y + bi1.y, f3.x + bi1.z, f3.y + bi1.w };
            float s = 0.f, ss = 0.f;
            #pragma unroll
            for (int j = 0; j < 8; j++) { s += v[j]; ss += v[j] * v[j]; }
            #pragma unroll
            for (int o = 8; o; o >>= 1) {
                s  += __shfl_xor_sync(0xffffffffu, s,  o);
                ss += __shfl_xor_sync(0xffffffffu, ss, o);
            }
            float mean = s * (1.0f / 128.0f);
            float var  = ss * (1.0f / 128.0f) - mean * mean;
            float rs   = rsqrtf(var + 1e-5f);
            float o0 = fmaxf(0.f, (v[0] - mean) * rs * gg0.x + ee0.x);
            float o1 = fmaxf(0.f, (v[1] - mean) * rs * gg0.y + ee0.y);
            float o2 = fmaxf(0.f, (v[2] - mean) * rs * gg0.z + ee0.z);
            float o3 = fmaxf(0.f, (v[3] - mean) * rs * gg0.w + ee0.w);
            float o4 = fmaxf(0.f, (v[4] - mean) * rs * gg1.x + ee1.x);
            float o5 = fmaxf(0.f, (v[5] - mean) * rs * gg1.y + ee1.y);
            float o6 = fmaxf(0.f, (v[6] - mean) * rs * gg1.z + ee1.z);
            float o7 = fmaxf(0.f, (v[7] - mean) * rs * gg1.w + ee1.w);
            if (gr < N) {
                *(float4*)(H + (size_t)gr * 128 + tx * 4)      = make_float4(o0, o1, o2, o3);
                *(float4*)(H + (size_t)gr * 128 + 64 + tx * 4) = make_float4(o4, o5, o6, o7);
            }
        }
    } else {
        __half* Yh = (y == 1) ? A : B;
        #pragma unroll
        for (int i = 0; i < 8; i++) {
            int row = (i < 4) ? (ty * 4 + i) : (64 + ty * 4 + (i - 4));
            int gr = n0 + row;
            if (gr < N) {
                float2 f0 = unpack2(acc[i][0]), f1 = unpack2(acc[i][1]);
                float2 f2 = unpack2(acc[i][2]), f3 = unpack2(acc[i][3]);
                uint2 u0, u1;
                u0.x = h2u(__floats2half2_rn(f0.x, f0.y));
                u0.y = h2u(__floats2half2_rn(f1.x, f1.y));
                u1.x = h2u(__floats2half2_rn(f2.x, f2.y));
                u1.y = h2u(__floats2half2_rn(f3.x, f3.y));
                *(uint2*)(Yh + (size_t)gr * 128 + tx * 4)      = u0;
                *(uint2*)(Yh + (size_t)gr * 128 + 64 + tx * 4) = u1;
            }
        }
    }
}

// ---------------- T = H @ Wnc ----------------
__global__ __launch_bounds__(256, 2) void gemm_t_kernel(
    const float* __restrict__ H, float* __restrict__ T, int N)
{
    __shared__ float Xs2[128 * 64];
    __shared__ float Ws[BK * 128];
    int tid = threadIdx.x, tx = tid & 15, ty = tid >> 4;
    int n0 = blockIdx.x * 128;
    unsigned long long acc[8][4];
    #pragma unroll
    for (int i = 0; i < 8; i++)
        #pragma unroll
        for (int p = 0; p < 4; p++) acc[i][p] = 0ULL;

    gemm_pass(H, g_Wnc, n0, N, tid, tx, ty, Xs2, Ws, acc);

    #pragma unroll
    for (int i = 0; i < 8; i++) {
        int row = (i < 4) ? (ty * 4 + i) : (64 + ty * 4 + (i - 4));
        int gr = n0 + row;
        if (gr < N) {
            float2 f0 = unpack2(acc[i][0]), f1 = unpack2(acc[i][1]);
            float2 f2 = unpack2(acc[i][2]), f3 = unpack2(acc[i][3]);
            *(float4*)(T + (size_t)gr * 128 + tx * 4)      = make_float4(f0.x, f0.y, f1.x, f1.y);
            *(float4*)(T + (size_t)gr * 128 + 64 + tx * 4) = make_float4(f2.x, f2.y, f3.x, f3.y);
        }
    }
}

// ---------------- final: out = LN(T + S@Wec + x + cbias + deg*evec) ----------------
__global__ __launch_bounds__(256, 2) void final_kernel(
    const float* __restrict__ T, const float* __restrict__ S,
    const float* __restrict__ x, const float* __restrict__ deg,
    const float* __restrict__ lng, const float* __restrict__ lnb,
    float* __restrict__ Y, int N)
{
    __shared__ float Xs2[128 * 64];
    __shared__ float Ws[BK * 128];
    int tid = threadIdx.x, tx = tid & 15, ty = tid >> 4;
    int n0 = blockIdx.x * 128;
    unsigned long long acc[8][4];
    #pragma unroll
    for (int i = 0; i < 8; i++)
        #pragma unroll
        for (int p = 0; p < 4; p++) acc[i][p] = 0ULL;

    gemm_pass(S, g_Wec, n0, N, tid, tx, ty, Xs2, Ws, acc);

    float4 cb0 = *(const float4*)(g_cbias + tx * 4);
    float4 cb1 = *(const float4*)(g_cbias + 64 + tx * 4);
    float4 ev0 = *(const float4*)(g_evec + tx * 4);
    float4 ev1 = *(const float4*)(g_evec + 64 + tx * 4);
    float4 gg0 = *(const float4*)(lng + tx * 4);
    float4 gg1 = *(const float4*)(lng + 64 + tx * 4);
    float4 bb0 = *(const float4*)(lnb + tx * 4);
    float4 bb1 = *(const float4*)(lnb + 64 + tx * 4);

    #pragma unroll
    for (int i = 0; i < 8; i++) {
        int row = (i < 4) ? (ty * 4 + i) : (64 + ty * 4 + (i - 4));
        int gr = n0 + row;
        int gl = (gr > N - 1) ? (N - 1) : gr;
        float d = deg[gl];
        float4 xr0 = *(const float4*)(x + (size_t)gl * 128 + tx * 4);
        float4 xr1 = *(const float4*)(x + (size_t)gl * 128 + 64 + tx * 4);
        float4 tr0 = *(const float4*)(T + (size_t)gl * 128 + tx * 4);
        float4 tr1 = *(const float4*)(T + (size_t)gl * 128 + 64 + tx * 4);
        float2 f0 = unpack2(acc[i][0]), f1 = unpack2(acc[i][1]);
        float2 f2 = unpack2(acc[i][2]), f3 = unpack2(acc[i][3]);
        float v[8];
        v[0] = f0.x + tr0.x + xr0.x + cb0.x + d * ev0.x;
        v[1] = f0.y + tr0.y + xr0.y + cb0.y + d * ev0.y;
        v[2] = f1.x + tr0.z + xr0.z + cb0.z + d * ev0.z;
        v[3] = f1.y + tr0.w + xr0.w + cb0.w + d * ev0.w;
        v[4] = f2.x + tr1.x + xr1.x + cb1.x + d * ev1.x;
        v[5] = f2.y + tr1.y + xr1.y + cb1.y + d * ev1.y;
        v[6] = f3.x + tr1.z + xr1.z + cb1.z + d * ev1.z;
        v[7] = f3.y + tr1.w + xr1.w + cb1.w + d * ev1.w;
        float s = 0.f, ss = 0.f;
        #pragma unroll
        for (int j = 0; j < 8; j++) { s += v[j]; ss += v[j] * v[j]; }
        #pragma unroll
        for (int o = 8; o; o >>= 1) {
            s  += __shfl_xor_sync(0xffffffffu, s,  o);
            ss += __shfl_xor_sync(0xffffffffu, ss, o);
        }
        float mean = s * (1.0f / 128.0f);
        float var  = ss * (1.0f / 128.0f) - mean * mean;
        float rs   = rsqrtf(var + 1e-5f);
        float o0 = (v[0] - mean) * rs * gg0.x + bb0.x;
        float o1 = (v[1] - mean) * rs * gg0.y + bb0.y;
        float o2 = (v[2] - mean) * rs * gg0.z + bb0.z;
        float o3 = (v[3] - mean) * rs * gg0.w + bb0.w;
        float o4 = (v[4] - mean) * rs * gg1.x + bb1.x;
        float o5 = (v[5] - mean) * rs * gg1.y + bb1.y;
        float o6 = (v[6] - mean) * rs * gg1.z + bb1.z;
        float o7 = (v[7] - mean) * rs * gg1.w + bb1.w;
        if (gr < N) {
            *(float4*)(Y + (size_t)gr * 128 + tx * 4)      = make_float4(o0, o1, o2, o3);
            *(float4*)(Y + (size_t)gr * 128 + 64 + tx * 4) = make_float4(o4, o5, o6, o7);
        }
    }
}

// ---------------- aggregation kernel: one warp per dst node, NO atomics ----------------
__global__ __launch_bounds__(256, 4) void agg_kernel(
    const __half* __restrict__ A, const __half* __restrict__ B,
    const int* __restrict__ off, const int* __restrict__ cnt,
    const int* __restrict__ esrc, const float4* __restrict__ ea4,
    const float* __restrict__ ea1,
    const float* __restrict__ W5, const float* __restrict__ eb1,
    const float* __restrict__ g1, const float* __restrict__ be1,
    float* __restrict__ S, float* __restrict__ deg, int N)
{
    __shared__ float sW5[5 * 128];
    __shared__ float sb[128], sg[128], sbe[128];
    int tid = threadIdx.x;
    for (int i = tid; i < 5 * 128; i += 256) sW5[i] = W5[i];
    if (tid < 128) { sb[tid] = eb1[tid]; sg[tid] = g1[tid]; sbe[tid] = be1[tid]; }
    __syncthreads();

    int lane = tid & 31;
    int gw = (blockIdx.x * 256 + tid) >> 5;
    int nw = (gridDim.x * 256) >> 5;
    int c = lane * 4;

    float4 w0 = *(const float4*)(sW5 + 0 * 128 + c);
    float4 w1 = *(const float4*)(sW5 + 1 * 128 + c);
    float4 w2 = *(const float4*)(sW5 + 2 * 128 + c);
    float4 w3 = *(const float4*)(sW5 + 3 * 128 + c);
    float4 w4 = *(const float4*)(sW5 + 4 * 128 + c);
    float4 sb4 = *(const float4*)(sb + c);
    float4 sg4 = *(const float4*)(sg + c);
    float4 se4 = *(const float4*)(sbe + c);

    for (int d = gw; d < N; d += nw) {
        int start = __ldg(off + d);
        int n     = __ldg(cnt + d);
        float a0 = 0.f, a1 = 0.f, a2 = 0.f, a3 = 0.f;

        if (n > 0) {
            uint2 rbu = __ldg((const uint2*)(B + (size_t)d * 128 + c));
            float2 blo = u2f2(rbu.x), bhi = u2f2(rbu.y);

            for (int k = 0; k < n; k += 2) {
                int i0 = start + k;
                bool v1 = (k + 1 < n);
                int i1 = v1 ? i0 + 1 : i0;

                int s0 = __ldg(esrc + i0);
                int s1 = __ldg(esrc + i1);
                float4 eA = __ldg(ea4 + i0);
                float  e4a = __ldg(ea1 + i0);
                float4 eB = __ldg(ea4 + i1);
                float  e4b = __ldg(ea1 + i1);

                uint2 ra0 = __ldg((const uint2*)(A + (size_t)s0 * 128 + c));
                uint2 ra1 = __ldg((const uint2*)(A + (size_t)s1 * 128 + c));
                float2 x0lo = u2f2(ra0.x), x0hi = u2f2(ra0.y);
                float2 x1lo = u2f2(ra1.x), x1hi = u2f2(ra1.y);

                float b00 = sb4.x + blo.x + eA.x * w0.x + eA.y * w1.x + eA.z * w2.x + eA.w * w3.x + e4a * w4.x;
                float b01 = sb4.y + blo.y + eA.x * w0.y + eA.y * w1.y + eA.z * w2.y + eA.w * w3.y + e4a * w4.y;
                float b02 = sb4.z + bhi.x + eA.x * w0.z + eA.y * w1.z + eA.z * w2.z + eA.w * w3.z + e4a * w4.z;
                float b03 = sb4.w + bhi.y + eA.x * w0.w + eA.y * w1.w + eA.z * w2.w + eA.w * w3.w + e4a * w4.w;
                float p00 = x0lo.x + b00;
                float p01 = x0lo.y + b01;
                float p02 = x0hi.x + b02;
                float p03 = x0hi.y + b03;

                float b10 = sb4.x + blo.x + eB.x * w0.x + eB.y * w1.x + eB.z * w2.x + eB.w * w3.x + e4b * w4.x;
                float b11 = sb4.y + blo.y + eB.x * w0.y + eB.y * w1.y + eB.z * w2.y + eB.w * w3.y + e4b * w4.y;
                float b12 = sb4.z + bhi.x + eB.x * w0.z + eB.y * w1.z + eB.z * w2.z + eB.w * w3.z + e4b * w4.z;
                float b13 = sb4.w + bhi.y + eB.x * w0.w + eB.y * w1.w + eB.z * w2.w + eB.w * w3.w + e4b * w4.w;
                float p10 = x1lo.x + b10;
                float p11 = x1lo.y + b11;
                float p12 = x1hi.x + b12;
                float p13 = x1hi.y + b13;

                float su0 = p00 + p01 + p02 + p03;
                float q0  = p00 * p00 + p01 * p01 + p02 * p02 + p03 * p03;
                float su1 = p10 + p11 + p12 + p13;
                float q1  = p10 * p10 + p11 * p11 + p12 * p12 + p13 * p13;
                #pragma unroll
                for (int o = 16; o; o >>= 1) {
                    su0 += __shfl_xor_sync(0xffffffffu, su0, o);
                    q0  += __shfl_xor_sync(0xffffffffu, q0,  o);
                    su1 += __shfl_xor_sync(0xffffffffu, su1, o);
                    q1  += __shfl_xor_sync(0xffffffffu, q1,  o);
                }
                float mean0 = su0 * (1.0f / 128.0f);
                float rs0   = rsqrtf(q0 * (1.0f / 128.0f) - mean0 * mean0 + 1e-5f);
                float mean1 = su1 * (1.0f / 128.0f);
                float rs1   = rsqrtf(q1 * (1.0f / 128.0f) - mean1 * mean1 + 1e-5f);

                a0 += fmaxf(0.f, (p00 - mean0) * rs0 * sg4.x + se4.x);
                a1 += fmaxf(0.f, (p01 - mean0) * rs0 * sg4.y + se4.y);
                a2 += fmaxf(0.f, (p02 - mean0) * rs0 * sg4.z + se4.z);
                a3 += fmaxf(0.f, (p03 - mean0) * rs0 * sg4.w + se4.w);
                if (v1) {
                    a0 += fmaxf(0.f, (p10 - mean1) * rs1 * sg4.x + se4.x);
                    a1 += fmaxf(0.f, (p11 - mean1) * rs1 * sg4.y + se4.y);
                    a2 += fmaxf(0.f, (p12 - mean1) * rs1 * sg4.z + se4.z);
                    a3 += fmaxf(0.f, (p13 - mean1) * rs1 * sg4.w + se4.w);
                }
            }
        }
        *(float4*)(S + (size_t)d * 128 + c) = make_float4(a0, a1, a2, a3);
        if (lane == 0) deg[d] = (float)n;
    }
}

// ---------------- prep kernel ----------------
__global__ __launch_bounds__(256, 2) void prep_kernel(
    const float* __restrict__ w2n, const float* __restrict__ w2e,
    const float* __restrict__ U,
    const float* __restrict__ bn2, const float* __restrict__ be2,
    const float* __restrict__ ub,
    float* __restrict__ Wnc, float* __restrict__ Wec,
    float* __restrict__ cb, float* __restrict__ ev)
{
    __shared__ float Xs2[128 * 64];
    __shared__ float Ws[BK * 128];
    int tid = threadIdx.x, tx = tid & 15, ty = tid >> 4;
    int y = blockIdx.y;

    if (y == 2) {
        int j = tid & 127, h = tid >> 7;
        float a = 0.f, b = 0.f;
        int m0 = h * 64;
        #pragma unroll 16
        for (int m = m0; m < m0 + 64; m++) {
            a += bn2[m] * U[m * 128 + j];
            b += be2[m] * U[(128 + m) * 128 + j];
        }
        Xs2[tid] = a;
        Xs2[512 + tid] = b;
        __syncthreads();
        if (h == 0) {
            cb[j] = Xs2[j] + Xs2[128 + j] + ub[j];
            ev[j] = Xs2[512 + j] + Xs2[640 + j];
        }
        return;
    }

    const float* X = y ? w2e : w2n;
    const float* W = y ? (U + 128 * 128) : U;
    float* out = y ? Wec : Wnc;

    unsigned long long acc[8][4];
    #pragma unroll
    for (int i = 0; i < 8; i++)
        #pragma unroll
        for (int p = 0; p < 4; p++) acc[i][p] = 0ULL;

    gemm_pass(X, W, 0, 128, tid, tx, ty, Xs2, Ws, acc);

    #pragma unroll
    for (int i = 0; i < 8; i++) {
        int row = (i < 4) ? (ty * 4 + i) : (64 + ty * 4 + (i - 4));
        float2 f0 = unpack2(acc[i][0]), f1 = unpack2(acc[i][1]);
        float2 f2 = unpack2(acc[i][2]), f3 = unpack2(acc[i][3]);
        *(float4*)(out + (size_t)row * 128 + tx * 4)      = make_float4(f0.x, f0.y, f1.x, f1.y);
        *(float4*)(out + (size_t)row * 128 + 64 + tx * 4) = make_float4(f2.x, f2.y, f3.x, f3.y);
    }
}

// ---------------- launch ----------------
extern "C" void kernel_launch(void* const* d_in, const int* in_sizes, int n_in,
                              void* d_out, int out_size)
{
    const float* x         = (const float*)d_in[0];
    const float* edge_attr = (const float*)d_in[1];
    const float* node_w1   = (const float*)d_in[3];
    const float* node_b1   = (const float*)d_in[4];
    const float* node_g1   = (const float*)d_in[5];
    const float* node_be1  = (const float*)d_in[6];
    const float* node_w2   = (const float*)d_in[7];
    const float* node_b2   = (const float*)d_in[8];
    const float* edge_w1   = (const float*)d_in[9];
    const float* edge_b1   = (const float*)d_in[10];
    const float* edge_g1   = (const float*)d_in[11];
    const float* edge_be1  = (const float*)d_in[12];
    const float* edge_w2   = (const float*)d_in[13];
    const float* edge_b2   = (const float*)d_in[14];
    const float* upd_w     = (const float*)d_in[15];
    const float* upd_b     = (const float*)d_in[16];
    const float* ln_g      = (const float*)d_in[17];
    const float* ln_b      = (const float*)d_in[18];
    const void*  ei        = d_in[19];
    float* out = (float*)d_out;

    int N = in_sizes[0] / 128;
    int E = in_sizes[19] / 2;

    float *pH, *pS, *pT, *pdeg, *pWnc, *pWec, *pcb, *pev, *pea1;
    __half *pA, *pB;
    int *pcnt, *ploc, *pbtot, *poff, *pcur, *pesrc;
    float4 *pea4;
    cudaGetSymbolAddress((void**)&pH,    g_H1n);
    cudaGetSymbolAddress((void**)&pA,    g_A);
    cudaGetSymbolAddress((void**)&pB,    g_B);
    cudaGetSymbolAddress((void**)&pS,    g_S);
    cudaGetSymbolAddress((void**)&pT,    g_T);
    cudaGetSymbolAddress((void**)&pdeg,  g_deg);
    cudaGetSymbolAddress((void**)&pWnc,  g_Wnc);
    cudaGetSymbolAddress((void**)&pWec,  g_Wec);
    cudaGetSymbolAddress((void**)&pcb,   g_cbias);
    cudaGetSymbolAddress((void**)&pev,   g_evec);
    cudaGetSymbolAddress((void**)&pcnt,  g_cnt);
    cudaGetSymbolAddress((void**)&ploc,  g_loc);
    cudaGetSymbolAddress((void**)&pbtot, g_btot);
    cudaGetSymbolAddress((void**)&poff,  g_off);
    cudaGetSymbolAddress((void**)&pcur,  g_cur);
    cudaGetSymbolAddress((void**)&pesrc, g_esrc);
    cudaGetSymbolAddress((void**)&pea4,  g_ea4);
    cudaGetSymbolAddress((void**)&pea1,  g_ea1);

    static cudaStream_t s1 = 0;
    static cudaEvent_t eFork = 0, eCSR = 0, eJoin = 0;
    if (!s1) cudaStreamCreateWithFlags(&s1, cudaStreamNonBlocking);
    if (!eFork) cudaEventCreateWithFlags(&eFork, cudaEventDisableTiming);
    if (!eCSR) cudaEventCreateWithFlags(&eCSR, cudaEventDisableTiming);
    if (!eJoin) cudaEventCreateWithFlags(&eJoin, cudaEventDisableTiming);

    cudaStream_t s0 = cudaStreamLegacy;
    {
        cudaStreamCaptureStatus st = cudaStreamCaptureStatusNone;
        if (cudaStreamIsCapturing(cudaStreamLegacy, &st) == cudaSuccess &&
            st == cudaStreamCaptureStatusActive) {
            s0 = cudaStreamLegacy;
        } else {
            cudaStreamCaptureStatus st2 = cudaStreamCaptureStatusNone;
            if (cudaStreamIsCapturing(cudaStreamPerThread, &st2) == cudaSuccess &&
                st2 == cudaStreamCaptureStatusActive) {
                s0 = cudaStreamPerThread;
            }
        }
    }

    int gb = (N + 127) / 128;
    int sb = (N + 1023) / 1024;   // scan blocks
    int nwords = 2 * E; if (nwords > 1024) nwords = 1024;

    // fork
    cudaEventRecord(eFork, s0);
    cudaStreamWaitEvent(s1, eFork, 0);

    // s0 #1: A,B GEMMs (critical path head)
    gemm_nab_kernel<<<dim3(gb, 2), 256, 0, s0>>>(x, node_w1, edge_w1,
                                                 node_b1, node_g1, node_be1,
                                                 pH, pA, pB, N, /*ybase=*/1);

    // s1: CSR build chain (hidden under AB GEMM)
    detect_zero_kernel<<<(N + 255) / 256, 256, 0, s1>>>(
        (const unsigned int*)ei, nwords, pcnt, N);
    count_kernel<<<592, 256, 0, s1>>>(ei, pcnt, E, N);
    scan_local_kernel<<<sb, 1024, 0, s1>>>(pcnt, ploc, pbtot, N);
    scan_fix_kernel<<<sb, 1024, 0, s1>>>(ploc, pbtot, poff, pcur, N);
    reorder_kernel<<<592, 256, 0, s1>>>(ei, edge_attr, pcur, pesrc, pea4, pea1, E, N);
    cudaEventRecord(eCSR, s1);

    // s1: prep (weight folding)
    prep_kernel<<<dim3(1, 3), 256, 0, s1>>>(node_w2, edge_w2, upd_w,
                                            node_b2, edge_b2, upd_b,
                                            pWnc, pWec, pcb, pev);

    // s0: aggregation (needs AB GEMM on s0 + CSR from s1); no atomics
    cudaStreamWaitEvent(s0, eCSR, 0);
    agg_kernel<<<592, 256, 0, s0>>>(pA, pB, poff, pcnt, pesrc, pea4, pea1,
                                    edge_w1 + 256 * 128, edge_b1, edge_g1, edge_be1,
                                    pS, pdeg, N);

    // s1: H GEMM + T = H @ Wnc (overlap aggregation)
    gemm_nab_kernel<<<dim3(gb, 1), 256, 0, s1>>>(x, node_w1, edge_w1,
                                                 node_b1, node_g1, node_be1,
                                                 pH, pA, pB, N, /*ybase=*/0);
    gemm_t_kernel<<<gb, 256, 0, s1>>>(pH, pT, N);

    // join
    cudaEventRecord(eJoin, s1);
    cudaStreamWaitEvent(s0, eJoin, 0);

    // s0: final
    final_kernel<<<gb, 256, 0, s0>>>(pT, pS, x, pdeg, ln_g, ln_b, out, N);
}